// round 7
// baseline (speedup 1.0000x reference)
#include <cuda_runtime.h>
#include <cuda_bf16.h>
#include <cstdint>

// Problem constants (from reference)
#define N_NODES 100000
#define D_IN    256
#define D_OUT   128

// Scratch for support = x @ W   (51.2 MB, __device__ global per harness rules)
__device__ float g_support[(size_t)N_NODES * D_OUT];

// ---------------------------------------------------------------------------
// SGEMM: C[M,128] = A[M,256] @ B[256,128], fp32, 128x128 block tile, 8x8 thread tile
// ---------------------------------------------------------------------------
#define BM 128
#define BN 128
#define BK 16

__global__ __launch_bounds__(256, 2)
void gemm_kernel(const float* __restrict__ A, const float* __restrict__ B,
                 float* __restrict__ C, int M) {
    __shared__ float As[BK][BM];   // transposed A tile
    __shared__ float Bs[BK][BN];

    const int tid  = threadIdx.x;
    const int row0 = blockIdx.x * BM;

    const int tx = tid % 16;       // 0..15 -> col group
    const int ty = tid / 16;       // 0..15 -> row group

    // Global-load mapping
    const int aRow = tid / 4;            // 0..63 (two passes: +0, +64)
    const int aCol = (tid % 4) * 4;      // 0,4,8,12 within BK
    const int bRow = tid / 32;           // 0..7 (two passes: +0, +8)
    const int bCol = (tid % 32) * 4;     // 0..124

    float acc[8][8];
    #pragma unroll
    for (int i = 0; i < 8; i++)
        #pragma unroll
        for (int j = 0; j < 8; j++) acc[i][j] = 0.0f;

    for (int k0 = 0; k0 < D_IN; k0 += BK) {
        // Load A tile (128x16), store transposed into As[k][m]
        #pragma unroll
        for (int i = 0; i < 2; i++) {
            int r  = aRow + i * 64;
            int gr = row0 + r;
            float4 v = make_float4(0.f, 0.f, 0.f, 0.f);
            if (gr < M)
                v = *(const float4*)(A + (size_t)gr * D_IN + k0 + aCol);
            As[aCol + 0][r] = v.x;
            As[aCol + 1][r] = v.y;
            As[aCol + 2][r] = v.z;
            As[aCol + 3][r] = v.w;
        }
        // Load B tile (16x128), row-major direct
        #pragma unroll
        for (int i = 0; i < 2; i++) {
            int r = bRow + i * 8;
            float4 v = *(const float4*)(B + (size_t)(k0 + r) * D_OUT + bCol);
            *(float4*)&Bs[r][bCol] = v;
        }
        __syncthreads();

        #pragma unroll
        for (int k = 0; k < BK; k++) {
            float a[8], b[8];
            *(float4*)&a[0] = *(const float4*)&As[k][ty * 8];
            *(float4*)&a[4] = *(const float4*)&As[k][ty * 8 + 4];
            *(float4*)&b[0] = *(const float4*)&Bs[k][tx * 8];
            *(float4*)&b[4] = *(const float4*)&Bs[k][tx * 8 + 4];
            #pragma unroll
            for (int i = 0; i < 8; i++)
                #pragma unroll
                for (int j = 0; j < 8; j++)
                    acc[i][j] += a[i] * b[j];
        }
        __syncthreads();
    }

    // Store 8x8 per thread (float4 x2 per row)
    #pragma unroll
    for (int i = 0; i < 8; i++) {
        int gr = row0 + ty * 8 + i;
        if (gr < M) {
            float* cp = C + (size_t)gr * D_OUT + tx * 8;
            *(float4*)(cp)     = *(float4*)&acc[i][0];
            *(float4*)(cp + 4) = *(float4*)&acc[i][4];
        }
    }
}

// ---------------------------------------------------------------------------
// Scatter: one warp per edge. Lane l handles floats [4l, 4l+4) of the 128-dim row.
// gather support[src], scale by w, red.global.add.v4.f32 into out[dst].
// ---------------------------------------------------------------------------
__global__ __launch_bounds__(256)
void scatter_kernel(const float* __restrict__ support,
                    const int*   __restrict__ src,
                    const int*   __restrict__ dst,
                    const float* __restrict__ ew,
                    float*       __restrict__ out,
                    int nE) {
    int gw   = (int)((blockIdx.x * (unsigned)blockDim.x + threadIdx.x) >> 5);
    int lane = threadIdx.x & 31;
    if (gw >= nE) return;

    int   s  = __ldg(src + gw);
    int   d  = __ldg(dst + gw);
    float wt = __ldg(ew  + gw);

    float4 v = *(const float4*)(support + (size_t)s * D_OUT + lane * 4);
    v.x *= wt; v.y *= wt; v.z *= wt; v.w *= wt;

    float* p = out + (size_t)d * D_OUT + lane * 4;
    asm volatile("red.global.add.v4.f32 [%0], {%1, %2, %3, %4};"
                 :: "l"(p), "f"(v.x), "f"(v.y), "f"(v.z), "f"(v.w)
                 : "memory");
}

// ---------------------------------------------------------------------------
// Launcher
// Inputs (metadata order): x[f32 N*256], edge_src[i32 E], edge_dst[i32 E],
//                          edge_weight[f32 E], W[f32 256*128]
// Output: out[f32 N*128]
// ---------------------------------------------------------------------------
extern "C" void kernel_launch(void* const* d_in, const int* in_sizes, int n_in,
                              void* d_out, int out_size) {
    const float* x   = (const float*)d_in[0];
    const int*   esrc = (const int*)d_in[1];
    const int*   edst = (const int*)d_in[2];
    const float* ew  = (const float*)d_in[3];
    const float* W   = (const float*)d_in[4];
    float* out = (float*)d_out;

    const int nE = in_sizes[1];

    float* support;
    cudaGetSymbolAddress((void**)&support, g_support);

    // 1) zero output (memset node — graph-capturable)
    cudaMemsetAsync(d_out, 0, (size_t)out_size * sizeof(float));

    // 2) support = x @ W
    {
        dim3 grid((N_NODES + BM - 1) / BM);
        gemm_kernel<<<grid, 256>>>(x, W, support, N_NODES);
    }

    // 3) out[dst] += w * support[src]   (one warp per edge)
    {
        long long totalThreads = (long long)nE * 32;
        int blocks = (int)((totalThreads + 255) / 256);
        scatter_kernel<<<blocks, 256>>>(support, esrc, edst, ew, out, nE);
    }
}

// round 9
// speedup vs baseline: 1.1701x; 1.1701x over previous
#include <cuda_runtime.h>
#include <cuda_bf16.h>
#include <cstdint>

// Problem constants (from reference)
#define N_NODES 100000
#define D_IN    256
#define D_OUT   128
#define N_EDGES_MAX 3200000

// ---------------------------------------------------------------------------
// Device scratch (no allocs allowed in kernel_launch)
// ---------------------------------------------------------------------------
__device__ float g_support[(size_t)N_NODES * D_OUT];   // 51.2 MB
__device__ int   g_cnt[N_NODES];                       // per-dst edge counts
__device__ int   g_rowptr[N_NODES + 1];                // CSR row pointers
__device__ int   g_cursor[N_NODES];                    // fill cursors
__device__ int2  g_pairs[N_EDGES_MAX];                 // (src, w_bits) sorted by dst

// ---------------------------------------------------------------------------
// SGEMM: C[M,128] = A[M,256] @ B[256,128], fp32, 128x128 block tile, 8x8 thread tile
// (unchanged — proven correct)
// ---------------------------------------------------------------------------
#define BM 128
#define BN 128
#define BK 16

__global__ __launch_bounds__(256, 2)
void gemm_kernel(const float* __restrict__ A, const float* __restrict__ B,
                 float* __restrict__ C, int M) {
    __shared__ float As[BK][BM];   // transposed A tile
    __shared__ float Bs[BK][BN];

    const int tid  = threadIdx.x;
    const int row0 = blockIdx.x * BM;

    const int tx = tid % 16;       // 0..15 -> col group
    const int ty = tid / 16;       // 0..15 -> row group

    const int aRow = tid / 4;            // 0..63 (two passes: +0, +64)
    const int aCol = (tid % 4) * 4;      // 0,4,8,12 within BK
    const int bRow = tid / 32;           // 0..7 (two passes: +0, +8)
    const int bCol = (tid % 32) * 4;     // 0..124

    float acc[8][8];
    #pragma unroll
    for (int i = 0; i < 8; i++)
        #pragma unroll
        for (int j = 0; j < 8; j++) acc[i][j] = 0.0f;

    for (int k0 = 0; k0 < D_IN; k0 += BK) {
        #pragma unroll
        for (int i = 0; i < 2; i++) {
            int r  = aRow + i * 64;
            int gr = row0 + r;
            float4 v = make_float4(0.f, 0.f, 0.f, 0.f);
            if (gr < M)
                v = *(const float4*)(A + (size_t)gr * D_IN + k0 + aCol);
            As[aCol + 0][r] = v.x;
            As[aCol + 1][r] = v.y;
            As[aCol + 2][r] = v.z;
            As[aCol + 3][r] = v.w;
        }
        #pragma unroll
        for (int i = 0; i < 2; i++) {
            int r = bRow + i * 8;
            float4 v = *(const float4*)(B + (size_t)(k0 + r) * D_OUT + bCol);
            *(float4*)&Bs[r][bCol] = v;
        }
        __syncthreads();

        #pragma unroll
        for (int k = 0; k < BK; k++) {
            float a[8], b[8];
            *(float4*)&a[0] = *(const float4*)&As[k][ty * 8];
            *(float4*)&a[4] = *(const float4*)&As[k][ty * 8 + 4];
            *(float4*)&b[0] = *(const float4*)&Bs[k][tx * 8];
            *(float4*)&b[4] = *(const float4*)&Bs[k][tx * 8 + 4];
            #pragma unroll
            for (int i = 0; i < 8; i++)
                #pragma unroll
                for (int j = 0; j < 8; j++)
                    acc[i][j] += a[i] * b[j];
        }
        __syncthreads();
    }

    #pragma unroll
    for (int i = 0; i < 8; i++) {
        int gr = row0 + ty * 8 + i;
        if (gr < M) {
            float* cp = C + (size_t)gr * D_OUT + tx * 8;
            *(float4*)(cp)     = *(float4*)&acc[i][0];
            *(float4*)(cp + 4) = *(float4*)&acc[i][4];
        }
    }
}

// ---------------------------------------------------------------------------
// Counting sort by dst, stage 1: histogram
// ---------------------------------------------------------------------------
__global__ __launch_bounds__(256)
void hist_kernel(const int* __restrict__ dst, int nE) {
    int e = blockIdx.x * blockDim.x + threadIdx.x;
    if (e < nE) atomicAdd(&g_cnt[dst[e]], 1);
}

// ---------------------------------------------------------------------------
// Stage 2: exclusive scan over g_cnt -> g_rowptr, g_cursor.  Single block.
// ---------------------------------------------------------------------------
__global__ __launch_bounds__(1024)
void scan_kernel() {
    __shared__ int sums[1024];
    const int t = threadIdx.x;
    const int chunk = (N_NODES + 1023) / 1024;          // 98
    const int beg = t * chunk;
    const int end = min(beg + chunk, N_NODES);

    int s = 0;
    for (int i = beg; i < end; i++) s += g_cnt[i];
    sums[t] = s;
    __syncthreads();

    // Hillis-Steele inclusive scan over 1024 partials
    #pragma unroll
    for (int off = 1; off < 1024; off <<= 1) {
        int v = (t >= off) ? sums[t - off] : 0;
        __syncthreads();
        sums[t] += v;
        __syncthreads();
    }

    int run = (t == 0) ? 0 : sums[t - 1];   // exclusive prefix for this chunk
    for (int i = beg; i < end; i++) {
        g_rowptr[i] = run;
        g_cursor[i] = run;
        run += g_cnt[i];
    }
    if (t == 1023) g_rowptr[N_NODES] = sums[1023];  // total edge count
}

// ---------------------------------------------------------------------------
// Stage 3: scatter (src, w) records into dst-sorted order
// ---------------------------------------------------------------------------
__global__ __launch_bounds__(256)
void fill_kernel(const int* __restrict__ src, const int* __restrict__ dst,
                 const float* __restrict__ ew, int nE) {
    int e = blockIdx.x * blockDim.x + threadIdx.x;
    if (e >= nE) return;
    int d = dst[e];
    int pos = atomicAdd(&g_cursor[d], 1);
    g_pairs[pos] = make_int2(src[e], __float_as_int(ew[e]));
}

// ---------------------------------------------------------------------------
// Stage 4: segmented gather-accumulate. One warp per node, lane l owns
// floats [4l, 4l+4) of the 128-dim row. No atomics: plain float4 store.
// ---------------------------------------------------------------------------
__global__ __launch_bounds__(256)
void gather_kernel(const float* __restrict__ support, float* __restrict__ out) {
    const int warp = (int)((blockIdx.x * (unsigned)blockDim.x + threadIdx.x) >> 5);
    const int lane = threadIdx.x & 31;
    if (warp >= N_NODES) return;

    const int beg = g_rowptr[warp];
    const int end = g_rowptr[warp + 1];

    float4 acc = make_float4(0.f, 0.f, 0.f, 0.f);

    for (int b = beg; b < end; b += 32) {
        const int m = min(32, end - b);
        int2 rec = make_int2(0, 0);
        if (lane < m) rec = g_pairs[b + lane];

        #pragma unroll 4
        for (int j = 0; j < m; j++) {
            int   s  = __shfl_sync(0xffffffffu, rec.x, j);
            float wt = __int_as_float(__shfl_sync(0xffffffffu, rec.y, j));
            const float4 v = *(const float4*)(support + (size_t)s * D_OUT + lane * 4);
            acc.x = fmaf(wt, v.x, acc.x);
            acc.y = fmaf(wt, v.y, acc.y);
            acc.z = fmaf(wt, v.z, acc.z);
            acc.w = fmaf(wt, v.w, acc.w);
        }
    }

    *(float4*)(out + (size_t)warp * D_OUT + lane * 4) = acc;
}

// ---------------------------------------------------------------------------
// Launcher
// Inputs (metadata order): x[f32 N*256], edge_src[i32 E], edge_dst[i32 E],
//                          edge_weight[f32 E], W[f32 256*128]
// Output: out[f32 N*128]
// ---------------------------------------------------------------------------
extern "C" void kernel_launch(void* const* d_in, const int* in_sizes, int n_in,
                              void* d_out, int out_size) {
    const float* x    = (const float*)d_in[0];
    const int*   esrc = (const int*)d_in[1];
    const int*   edst = (const int*)d_in[2];
    const float* ew   = (const float*)d_in[3];
    const float* W    = (const float*)d_in[4];
    float* out = (float*)d_out;

    const int nE = in_sizes[1];

    float* support;  cudaGetSymbolAddress((void**)&support, g_support);
    int*   cnt;      cudaGetSymbolAddress((void**)&cnt,     g_cnt);

    const int edgeBlocks = (nE + 255) / 256;

    // 1) zero histogram (memset node — graph-capturable). No out memset needed:
    //    gather_kernel stores every row, including zero-degree nodes.
    cudaMemsetAsync(cnt, 0, N_NODES * sizeof(int));

    // 2) support = x @ W
    gemm_kernel<<<(N_NODES + BM - 1) / BM, 256>>>(x, W, support, N_NODES);

    // 3) counting sort of edges by dst
    hist_kernel<<<edgeBlocks, 256>>>(edst, nE);
    scan_kernel<<<1, 1024>>>();
    fill_kernel<<<edgeBlocks, 256>>>(esrc, edst, ew, nE);

    // 4) segmented accumulate: one warp per node, no atomics
    {
        long long totalThreads = (long long)N_NODES * 32;
        int blocks = (int)((totalThreads + 255) / 256);
        gather_kernel<<<blocks, 256>>>(support, out);
    }
}

// round 13
// speedup vs baseline: 1.4006x; 1.1969x over previous
#include <cuda_runtime.h>
#include <cuda_bf16.h>
#include <cstdint>

// Problem constants (from reference)
#define N_NODES 100000
#define D_IN    256
#define D_OUT   128
#define N_EDGES_MAX 3200000

// ---------------------------------------------------------------------------
// Device scratch (no allocs allowed in kernel_launch)
// ---------------------------------------------------------------------------
__device__ float g_support[(size_t)N_NODES * D_OUT];   // 51.2 MB
__device__ int   g_cnt[N_NODES];                       // per-dst edge counts
__device__ int   g_rowptr[N_NODES + 1];                // CSR row pointers
__device__ int   g_cursor[N_NODES];                    // fill cursors
__device__ int2  g_pairs[N_EDGES_MAX];                 // (src, w_bits) sorted by dst

// ---------------------------------------------------------------------------
// Helpers
// ---------------------------------------------------------------------------
__device__ __forceinline__ uint32_t smem_to_u32(const void* p) {
    uint32_t a;
    asm("{ .reg .u64 t; cvta.to.shared.u64 t, %1; cvt.u32.u64 %0, t; }"
        : "=r"(a) : "l"(p));
    return a;
}
__device__ __forceinline__ uint32_t pack2(float a, float b) {
    __nv_bfloat162 t = __floats2bfloat162_rn(a, b);
    return *reinterpret_cast<uint32_t*>(&t);
}

// mma.sync m16n8k16 row.col f32.bf16.bf16.f32 (sm_80+ PTX, safe on compute_103)
__device__ __forceinline__ void mma16816(float* d, const uint32_t* a,
                                         const uint32_t* b) {
    asm volatile(
        "mma.sync.aligned.m16n8k16.row.col.f32.bf16.bf16.f32 "
        "{%0,%1,%2,%3}, {%4,%5,%6,%7}, {%8,%9}, {%0,%1,%2,%3};"
        : "+f"(d[0]), "+f"(d[1]), "+f"(d[2]), "+f"(d[3])
        : "r"(a[0]), "r"(a[1]), "r"(a[2]), "r"(a[3]), "r"(b[0]), "r"(b[1]));
}
__device__ __forceinline__ void ldm_x4(uint32_t* r, uint32_t addr) {
    asm volatile("ldmatrix.sync.aligned.m8n8.x4.shared.b16 {%0,%1,%2,%3}, [%4];"
                 : "=r"(r[0]), "=r"(r[1]), "=r"(r[2]), "=r"(r[3]) : "r"(addr));
}
__device__ __forceinline__ void ldm_x2(uint32_t* r, uint32_t addr) {
    asm volatile("ldmatrix.sync.aligned.m8n8.x2.shared.b16 {%0,%1}, [%2];"
                 : "=r"(r[0]), "=r"(r[1]) : "r"(addr));
}

// ---------------------------------------------------------------------------
// Tensor-core GEMM via mma.sync: support[M,128] = x[M,256] @ W[256,128]
// bf16 hi/lo split, 3 passes (hi*hi + hi*lo + lo*hi) for ~fp32 accuracy.
// CTA: 128 rows x 128 cols; K in 4 chunks of 64.
// SMEM rows padded to 144B (64 bf16 + 8 pad) -> ldmatrix conflict-free.
// ---------------------------------------------------------------------------
#define KC        64
#define ROW_BF16  72                      // 64 + 8 pad
#define ROW_BYTES (ROW_BF16 * 2)          // 144
#define TILE_B    (128 * ROW_BYTES)       // 18432
#define SM_AHI    0
#define SM_ALO    (TILE_B)
#define SM_BHI    (2 * TILE_B)
#define SM_BLO    (3 * TILE_B)
#define SM_TOTAL  (4 * TILE_B)            // 73728

__global__ __launch_bounds__(256, 2)
void gemm_mma_kernel(const float* __restrict__ A, const float* __restrict__ W,
                     float* __restrict__ C, int M) {
    extern __shared__ char smem[];
    const uint32_t sb   = smem_to_u32(smem);
    const int tid  = threadIdx.x;
    const int wid  = tid >> 5;
    const int lane = tid & 31;
    const int row0 = blockIdx.x * 128;
    const int m0   = wid * 16;            // warp's row strip within tile

    float acc[16][4];
    #pragma unroll
    for (int j = 0; j < 16; j++)
        #pragma unroll
        for (int q = 0; q < 4; q++) acc[j][q] = 0.0f;

    // Per-lane ldmatrix source coordinates (constant across k-steps)
    const int aRow = m0 + (lane & 7) + ((lane >> 3) & 1) * 8;  // within tile
    const int aKof = ((lane >> 4) & 1) * 8;                    // +0 or +8
    const int tb   = lane & 15;
    const int bRowL = (tb & 7);                                 // n within tile
    const int bKof  = ((tb >> 3) & 1) * 8;

    for (int c = 0; c < 4; c++) {
        const int k0 = c * KC;
        if (c > 0) __syncthreads();   // previous chunk's frags fully consumed

        // ---- convert A chunk: 128 rows x 64 cols fp32 -> bf16 hi/lo ----
        {
            const int r  = tid >> 1;
            const int gr = row0 + r;
            const int cb = (tid & 1) * 32;
            #pragma unroll
            for (int i = 0; i < 8; i++) {
                const int col = cb + i * 4;
                float4 v = make_float4(0.f, 0.f, 0.f, 0.f);
                if (gr < M)
                    v = *(const float4*)(A + (size_t)gr * D_IN + k0 + col);
                __nv_bfloat16 h0 = __float2bfloat16_rn(v.x);
                __nv_bfloat16 h1 = __float2bfloat16_rn(v.y);
                __nv_bfloat16 h2 = __float2bfloat16_rn(v.z);
                __nv_bfloat16 h3 = __float2bfloat16_rn(v.w);
                __nv_bfloat162 p01; p01.x = h0; p01.y = h1;
                __nv_bfloat162 p23; p23.x = h2; p23.y = h3;
                const uint32_t off = (uint32_t)r * ROW_BYTES + (uint32_t)col * 2;
                *(uint2*)(smem + SM_AHI + off) =
                    make_uint2(*(uint32_t*)&p01, *(uint32_t*)&p23);
                *(uint2*)(smem + SM_ALO + off) =
                    make_uint2(pack2(v.x - __bfloat162float(h0),
                                     v.y - __bfloat162float(h1)),
                               pack2(v.z - __bfloat162float(h2),
                                     v.w - __bfloat162float(h3)));
            }
        }
        // ---- convert B chunk: Bt[n][k] = W[k0+k][n], 128 x 64 ----
        {
            const int n  = tid >> 1;
            const int kb = (tid & 1) * 32;
            #pragma unroll
            for (int i = 0; i < 8; i++) {
                const int k = kb + i * 4;
                float w0 = W[(size_t)(k0 + k + 0) * D_OUT + n];
                float w1 = W[(size_t)(k0 + k + 1) * D_OUT + n];
                float w2 = W[(size_t)(k0 + k + 2) * D_OUT + n];
                float w3 = W[(size_t)(k0 + k + 3) * D_OUT + n];
                __nv_bfloat16 h0 = __float2bfloat16_rn(w0);
                __nv_bfloat16 h1 = __float2bfloat16_rn(w1);
                __nv_bfloat16 h2 = __float2bfloat16_rn(w2);
                __nv_bfloat16 h3 = __float2bfloat16_rn(w3);
                __nv_bfloat162 p01; p01.x = h0; p01.y = h1;
                __nv_bfloat162 p23; p23.x = h2; p23.y = h3;
                const uint32_t off = (uint32_t)n * ROW_BYTES + (uint32_t)k * 2;
                *(uint2*)(smem + SM_BHI + off) =
                    make_uint2(*(uint32_t*)&p01, *(uint32_t*)&p23);
                *(uint2*)(smem + SM_BLO + off) =
                    make_uint2(pack2(w0 - __bfloat162float(h0),
                                     w1 - __bfloat162float(h1)),
                               pack2(w2 - __bfloat162float(h2),
                                     w3 - __bfloat162float(h3)));
            }
        }
        __syncthreads();

        // ---- MMA main loop over this K-chunk ----
        #pragma unroll
        for (int ks = 0; ks < KC / 16; ks++) {
            const int k = ks * 16;
            const uint32_t aoff = (uint32_t)aRow * ROW_BYTES
                                + (uint32_t)(k + aKof) * 2;
            uint32_t ah[4], al[4];
            ldm_x4(ah, sb + SM_AHI + aoff);
            ldm_x4(al, sb + SM_ALO + aoff);

            #pragma unroll
            for (int j = 0; j < 16; j++) {
                const uint32_t boff = (uint32_t)(j * 8 + bRowL) * ROW_BYTES
                                    + (uint32_t)(k + bKof) * 2;
                uint32_t bh[2], bl[2];
                ldm_x2(bh, sb + SM_BHI + boff);
                ldm_x2(bl, sb + SM_BLO + boff);
                mma16816(acc[j], ah, bh);
                mma16816(acc[j], ah, bl);
                mma16816(acc[j], al, bh);
            }
        }
    }

    // ---- epilogue: write fp32 accumulators ----
    const int r0 = row0 + m0 + (lane >> 2);
    const int cc = (lane & 3) * 2;
    #pragma unroll
    for (int j = 0; j < 16; j++) {
        const int col = j * 8 + cc;
        if (r0 < M)
            *(float2*)(C + (size_t)r0 * D_OUT + col) =
                make_float2(acc[j][0], acc[j][1]);
        if (r0 + 8 < M)
            *(float2*)(C + (size_t)(r0 + 8) * D_OUT + col) =
                make_float2(acc[j][2], acc[j][3]);
    }
}

// ---------------------------------------------------------------------------
// Counting sort by dst, stage 1: histogram
// ---------------------------------------------------------------------------
__global__ __launch_bounds__(256)
void hist_kernel(const int* __restrict__ dst, int nE) {
    int e = blockIdx.x * blockDim.x + threadIdx.x;
    if (e < nE) atomicAdd(&g_cnt[dst[e]], 1);
}

// ---------------------------------------------------------------------------
// Stage 2: exclusive scan over g_cnt -> g_rowptr, g_cursor.  Single block.
// ---------------------------------------------------------------------------
__global__ __launch_bounds__(1024)
void scan_kernel() {
    __shared__ int sums[1024];
    const int t = threadIdx.x;
    const int chunk = (N_NODES + 1023) / 1024;          // 98
    const int beg = t * chunk;
    const int end = min(beg + chunk, N_NODES);

    int s = 0;
    for (int i = beg; i < end; i++) s += g_cnt[i];
    sums[t] = s;
    __syncthreads();

    #pragma unroll
    for (int off = 1; off < 1024; off <<= 1) {
        int v = (t >= off) ? sums[t - off] : 0;
        __syncthreads();
        sums[t] += v;
        __syncthreads();
    }

    int run = (t == 0) ? 0 : sums[t - 1];
    for (int i = beg; i < end; i++) {
        g_rowptr[i] = run;
        g_cursor[i] = run;
        run += g_cnt[i];
    }
    if (t == 1023) g_rowptr[N_NODES] = sums[1023];
}

// ---------------------------------------------------------------------------
// Stage 3: scatter (src, w) records into dst-sorted order
// ---------------------------------------------------------------------------
__global__ __launch_bounds__(256)
void fill_kernel(const int* __restrict__ src, const int* __restrict__ dst,
                 const float* __restrict__ ew, int nE) {
    int e = blockIdx.x * blockDim.x + threadIdx.x;
    if (e >= nE) return;
    int d = dst[e];
    int pos = atomicAdd(&g_cursor[d], 1);
    g_pairs[pos] = make_int2(src[e], __float_as_int(ew[e]));
}

// ---------------------------------------------------------------------------
// Stage 4: segmented gather-accumulate. One warp per node, no atomics.
// ---------------------------------------------------------------------------
__global__ __launch_bounds__(256)
void gather_kernel(const float* __restrict__ support, float* __restrict__ out) {
    const int warp = (int)((blockIdx.x * (unsigned)blockDim.x + threadIdx.x) >> 5);
    const int lane = threadIdx.x & 31;
    if (warp >= N_NODES) return;

    const int beg = g_rowptr[warp];
    const int end = g_rowptr[warp + 1];

    float4 acc = make_float4(0.f, 0.f, 0.f, 0.f);

    for (int b = beg; b < end; b += 32) {
        const int m = min(32, end - b);
        int2 rec = make_int2(0, 0);
        if (lane < m) rec = g_pairs[b + lane];

        #pragma unroll 4
        for (int j = 0; j < m; j++) {
            int   s  = __shfl_sync(0xffffffffu, rec.x, j);
            float wt = __int_as_float(__shfl_sync(0xffffffffu, rec.y, j));
            const float4 v = *(const float4*)(support + (size_t)s * D_OUT + lane * 4);
            acc.x = fmaf(wt, v.x, acc.x);
            acc.y = fmaf(wt, v.y, acc.y);
            acc.z = fmaf(wt, v.z, acc.z);
            acc.w = fmaf(wt, v.w, acc.w);
        }
    }

    *(float4*)(out + (size_t)warp * D_OUT + lane * 4) = acc;
}

// ---------------------------------------------------------------------------
// Launcher
// Inputs (metadata order): x[f32 N*256], edge_src[i32 E], edge_dst[i32 E],
//                          edge_weight[f32 E], W[f32 256*128]
// Output: out[f32 N*128]
// ---------------------------------------------------------------------------
extern "C" void kernel_launch(void* const* d_in, const int* in_sizes, int n_in,
                              void* d_out, int out_size) {
    const float* x    = (const float*)d_in[0];
    const int*   esrc = (const int*)d_in[1];
    const int*   edst = (const int*)d_in[2];
    const float* ew   = (const float*)d_in[3];
    const float* W    = (const float*)d_in[4];
    float* out = (float*)d_out;

    const int nE = in_sizes[1];

    float* support;  cudaGetSymbolAddress((void**)&support, g_support);
    int*   cnt;      cudaGetSymbolAddress((void**)&cnt,     g_cnt);

    const int edgeBlocks = (nE + 255) / 256;

    // 1) zero histogram (memset node — graph-capturable)
    cudaMemsetAsync(cnt, 0, N_NODES * sizeof(int));

    // 2) support = x @ W  (mma.sync bf16 hi/lo split, 3 passes)
    cudaFuncSetAttribute(gemm_mma_kernel,
                         cudaFuncAttributeMaxDynamicSharedMemorySize, SM_TOTAL);
    gemm_mma_kernel<<<(N_NODES + 127) / 128, 256, SM_TOTAL>>>(x, W, support, N_NODES);

    // 3) counting sort of edges by dst
    hist_kernel<<<edgeBlocks, 256>>>(edst, nE);
    scan_kernel<<<1, 1024>>>();
    fill_kernel<<<edgeBlocks, 256>>>(esrc, edst, ew, nE);

    // 4) segmented accumulate: one warp per node, no atomics
    {
        long long totalThreads = (long long)N_NODES * 32;
        int blocks = (int)((totalThreads + 255) / 256);
        gather_kernel<<<blocks, 256>>>(support, out);
    }
}

// round 17
// speedup vs baseline: 1.4701x; 1.0497x over previous
#include <cuda_runtime.h>
#include <cuda_bf16.h>
#include <cuda_fp16.h>
#include <cstdint>

// Problem constants (from reference)
#define N_NODES 100000
#define D_IN    256
#define D_OUT   128
#define N_EDGES_MAX 3200000

// ---------------------------------------------------------------------------
// Device scratch (no allocs allowed in kernel_launch)
// ---------------------------------------------------------------------------
__device__ __half g_support[(size_t)N_NODES * D_OUT]; // 25.6 MB (fp16 support)
__device__ int   g_cnt[N_NODES];                      // per-dst edge counts
__device__ int   g_rowptr[N_NODES + 1];               // CSR row pointers
__device__ int   g_cursor[N_NODES];                   // fill cursors
__device__ int2  g_pairs[N_EDGES_MAX];                // (src, w_bits) sorted by dst

// ---------------------------------------------------------------------------
// Helpers
// ---------------------------------------------------------------------------
__device__ __forceinline__ uint32_t smem_to_u32(const void* p) {
    uint32_t a;
    asm("{ .reg .u64 t; cvta.to.shared.u64 t, %1; cvt.u32.u64 %0, t; }"
        : "=r"(a) : "l"(p));
    return a;
}
__device__ __forceinline__ uint32_t pack2(float a, float b) {
    __nv_bfloat162 t = __floats2bfloat162_rn(a, b);
    return *reinterpret_cast<uint32_t*>(&t);
}

// mma.sync m16n8k16 row.col f32.bf16.bf16.f32 (sm_80+ PTX, safe on compute_103)
__device__ __forceinline__ void mma16816(float* d, const uint32_t* a,
                                         const uint32_t* b) {
    asm volatile(
        "mma.sync.aligned.m16n8k16.row.col.f32.bf16.bf16.f32 "
        "{%0,%1,%2,%3}, {%4,%5,%6,%7}, {%8,%9}, {%0,%1,%2,%3};"
        : "+f"(d[0]), "+f"(d[1]), "+f"(d[2]), "+f"(d[3])
        : "r"(a[0]), "r"(a[1]), "r"(a[2]), "r"(a[3]), "r"(b[0]), "r"(b[1]));
}
__device__ __forceinline__ void ldm_x4(uint32_t* r, uint32_t addr) {
    asm volatile("ldmatrix.sync.aligned.m8n8.x4.shared.b16 {%0,%1,%2,%3}, [%4];"
                 : "=r"(r[0]), "=r"(r[1]), "=r"(r[2]), "=r"(r[3]) : "r"(addr));
}
__device__ __forceinline__ void ldm_x2(uint32_t* r, uint32_t addr) {
    asm volatile("ldmatrix.sync.aligned.m8n8.x2.shared.b16 {%0,%1}, [%2];"
                 : "=r"(r[0]), "=r"(r[1]) : "r"(addr));
}

// ---------------------------------------------------------------------------
// Tensor-core GEMM via mma.sync: support[M,128] = x[M,256] @ W[256,128]
// bf16 hi/lo split, 3 passes (hi*hi + hi*lo + lo*hi) for ~fp32 accuracy.
// CTA: 128 rows x 128 cols; K in 4 chunks of 64.
// SMEM rows padded to 144B (64 bf16 + 8 pad) -> ldmatrix conflict-free.
// Epilogue stores fp16 (support consumed by gather; halves gather traffic).
// ---------------------------------------------------------------------------
#define KC        64
#define ROW_BF16  72                      // 64 + 8 pad
#define ROW_BYTES (ROW_BF16 * 2)          // 144
#define TILE_B    (128 * ROW_BYTES)       // 18432
#define SM_AHI    0
#define SM_ALO    (TILE_B)
#define SM_BHI    (2 * TILE_B)
#define SM_BLO    (3 * TILE_B)
#define SM_TOTAL  (4 * TILE_B)            // 73728

__global__ __launch_bounds__(256, 2)
void gemm_mma_kernel(const float* __restrict__ A, const float* __restrict__ W,
                     __half* __restrict__ C, int M) {
    extern __shared__ char smem[];
    const uint32_t sb   = smem_to_u32(smem);
    const int tid  = threadIdx.x;
    const int wid  = tid >> 5;
    const int lane = tid & 31;
    const int row0 = blockIdx.x * 128;
    const int m0   = wid * 16;            // warp's row strip within tile

    float acc[16][4];
    #pragma unroll
    for (int j = 0; j < 16; j++)
        #pragma unroll
        for (int q = 0; q < 4; q++) acc[j][q] = 0.0f;

    // Per-lane ldmatrix source coordinates (constant across k-steps)
    const int aRow = m0 + (lane & 7) + ((lane >> 3) & 1) * 8;  // within tile
    const int aKof = ((lane >> 4) & 1) * 8;                    // +0 or +8
    const int tb   = lane & 15;
    const int bRowL = (tb & 7);                                 // n within tile
    const int bKof  = ((tb >> 3) & 1) * 8;

    for (int c = 0; c < 4; c++) {
        const int k0 = c * KC;
        if (c > 0) __syncthreads();   // previous chunk's frags fully consumed

        // ---- convert A chunk: 128 rows x 64 cols fp32 -> bf16 hi/lo ----
        {
            const int r  = tid >> 1;
            const int gr = row0 + r;
            const int cb = (tid & 1) * 32;
            #pragma unroll
            for (int i = 0; i < 8; i++) {
                const int col = cb + i * 4;
                float4 v = make_float4(0.f, 0.f, 0.f, 0.f);
                if (gr < M)
                    v = *(const float4*)(A + (size_t)gr * D_IN + k0 + col);
                __nv_bfloat16 h0 = __float2bfloat16_rn(v.x);
                __nv_bfloat16 h1 = __float2bfloat16_rn(v.y);
                __nv_bfloat16 h2 = __float2bfloat16_rn(v.z);
                __nv_bfloat16 h3 = __float2bfloat16_rn(v.w);
                __nv_bfloat162 p01; p01.x = h0; p01.y = h1;
                __nv_bfloat162 p23; p23.x = h2; p23.y = h3;
                const uint32_t off = (uint32_t)r * ROW_BYTES + (uint32_t)col * 2;
                *(uint2*)(smem + SM_AHI + off) =
                    make_uint2(*(uint32_t*)&p01, *(uint32_t*)&p23);
                *(uint2*)(smem + SM_ALO + off) =
                    make_uint2(pack2(v.x - __bfloat162float(h0),
                                     v.y - __bfloat162float(h1)),
                               pack2(v.z - __bfloat162float(h2),
                                     v.w - __bfloat162float(h3)));
            }
        }
        // ---- convert B chunk: Bt[n][k] = W[k0+k][n], 128 x 64 ----
        {
            const int n  = tid >> 1;
            const int kb = (tid & 1) * 32;
            #pragma unroll
            for (int i = 0; i < 8; i++) {
                const int k = kb + i * 4;
                float w0 = W[(size_t)(k0 + k + 0) * D_OUT + n];
                float w1 = W[(size_t)(k0 + k + 1) * D_OUT + n];
                float w2 = W[(size_t)(k0 + k + 2) * D_OUT + n];
                float w3 = W[(size_t)(k0 + k + 3) * D_OUT + n];
                __nv_bfloat16 h0 = __float2bfloat16_rn(w0);
                __nv_bfloat16 h1 = __float2bfloat16_rn(w1);
                __nv_bfloat16 h2 = __float2bfloat16_rn(w2);
                __nv_bfloat16 h3 = __float2bfloat16_rn(w3);
                __nv_bfloat162 p01; p01.x = h0; p01.y = h1;
                __nv_bfloat162 p23; p23.x = h2; p23.y = h3;
                const uint32_t off = (uint32_t)n * ROW_BYTES + (uint32_t)k * 2;
                *(uint2*)(smem + SM_BHI + off) =
                    make_uint2(*(uint32_t*)&p01, *(uint32_t*)&p23);
                *(uint2*)(smem + SM_BLO + off) =
                    make_uint2(pack2(w0 - __bfloat162float(h0),
                                     w1 - __bfloat162float(h1)),
                               pack2(w2 - __bfloat162float(h2),
                                     w3 - __bfloat162float(h3)));
            }
        }
        __syncthreads();

        // ---- MMA main loop over this K-chunk ----
        #pragma unroll
        for (int ks = 0; ks < KC / 16; ks++) {
            const int k = ks * 16;
            const uint32_t aoff = (uint32_t)aRow * ROW_BYTES
                                + (uint32_t)(k + aKof) * 2;
            uint32_t ah[4], al[4];
            ldm_x4(ah, sb + SM_AHI + aoff);
            ldm_x4(al, sb + SM_ALO + aoff);

            #pragma unroll
            for (int j = 0; j < 16; j++) {
                const uint32_t boff = (uint32_t)(j * 8 + bRowL) * ROW_BYTES
                                    + (uint32_t)(k + bKof) * 2;
                uint32_t bh[2], bl[2];
                ldm_x2(bh, sb + SM_BHI + boff);
                ldm_x2(bl, sb + SM_BLO + boff);
                mma16816(acc[j], ah, bh);
                mma16816(acc[j], ah, bl);
                mma16816(acc[j], al, bh);
            }
        }
    }

    // ---- epilogue: fp32 accumulators -> fp16 support ----
    const int r0 = row0 + m0 + (lane >> 2);
    const int cc = (lane & 3) * 2;
    #pragma unroll
    for (int j = 0; j < 16; j++) {
        const int col = j * 8 + cc;
        if (r0 < M)
            *(__half2*)(C + (size_t)r0 * D_OUT + col) =
                __floats2half2_rn(acc[j][0], acc[j][1]);
        if (r0 + 8 < M)
            *(__half2*)(C + (size_t)(r0 + 8) * D_OUT + col) =
                __floats2half2_rn(acc[j][2], acc[j][3]);
    }
}

// ---------------------------------------------------------------------------
// Counting sort by dst, stage 1: histogram
// ---------------------------------------------------------------------------
__global__ __launch_bounds__(256)
void hist_kernel(const int* __restrict__ dst, int nE) {
    int e = blockIdx.x * blockDim.x + threadIdx.x;
    if (e < nE) atomicAdd(&g_cnt[dst[e]], 1);
}

// ---------------------------------------------------------------------------
// Stage 2: exclusive scan over g_cnt -> g_rowptr, g_cursor.  Single block.
// ---------------------------------------------------------------------------
__global__ __launch_bounds__(1024)
void scan_kernel() {
    __shared__ int sums[1024];
    const int t = threadIdx.x;
    const int chunk = (N_NODES + 1023) / 1024;          // 98
    const int beg = t * chunk;
    const int end = min(beg + chunk, N_NODES);

    int s = 0;
    for (int i = beg; i < end; i++) s += g_cnt[i];
    sums[t] = s;
    __syncthreads();

    #pragma unroll
    for (int off = 1; off < 1024; off <<= 1) {
        int v = (t >= off) ? sums[t - off] : 0;
        __syncthreads();
        sums[t] += v;
        __syncthreads();
    }

    int run = (t == 0) ? 0 : sums[t - 1];
    for (int i = beg; i < end; i++) {
        g_rowptr[i] = run;
        g_cursor[i] = run;
        run += g_cnt[i];
    }
    if (t == 1023) g_rowptr[N_NODES] = sums[1023];
}

// ---------------------------------------------------------------------------
// Stage 3: scatter (src, w) records into dst-sorted order
// ---------------------------------------------------------------------------
__global__ __launch_bounds__(256)
void fill_kernel(const int* __restrict__ src, const int* __restrict__ dst,
                 const float* __restrict__ ew, int nE) {
    int e = blockIdx.x * blockDim.x + threadIdx.x;
    if (e >= nE) return;
    int d = dst[e];
    int pos = atomicAdd(&g_cursor[d], 1);
    g_pairs[pos] = make_int2(src[e], __float_as_int(ew[e]));
}

// ---------------------------------------------------------------------------
// Stage 4: segmented gather-accumulate. One warp per node, no atomics.
// Lane l owns dims [4l, 4l+4): one 8B uint2 (2 x half2) per edge.
// ---------------------------------------------------------------------------
__global__ __launch_bounds__(256)
void gather_kernel(const __half* __restrict__ support, float* __restrict__ out) {
    const int warp = (int)((blockIdx.x * (unsigned)blockDim.x + threadIdx.x) >> 5);
    const int lane = threadIdx.x & 31;
    if (warp >= N_NODES) return;

    const int beg = g_rowptr[warp];
    const int end = g_rowptr[warp + 1];

    float4 acc = make_float4(0.f, 0.f, 0.f, 0.f);

    for (int b = beg; b < end; b += 32) {
        const int m = min(32, end - b);
        int2 rec = make_int2(0, 0);
        if (lane < m) rec = g_pairs[b + lane];

        #pragma unroll 4
        for (int j = 0; j < m; j++) {
            int   s  = __shfl_sync(0xffffffffu, rec.x, j);
            float wt = __int_as_float(__shfl_sync(0xffffffffu, rec.y, j));
            const uint2 u = *(const uint2*)(support + (size_t)s * D_OUT + lane * 4);
            const float2 f0 = __half22float2(*(const __half2*)&u.x);
            const float2 f1 = __half22float2(*(const __half2*)&u.y);
            acc.x = fmaf(wt, f0.x, acc.x);
            acc.y = fmaf(wt, f0.y, acc.y);
            acc.z = fmaf(wt, f1.x, acc.z);
            acc.w = fmaf(wt, f1.y, acc.w);
        }
    }

    *(float4*)(out + (size_t)warp * D_OUT + lane * 4) = acc;
}

// ---------------------------------------------------------------------------
// Launcher
// Inputs (metadata order): x[f32 N*256], edge_src[i32 E], edge_dst[i32 E],
//                          edge_weight[f32 E], W[f32 256*128]
// Output: out[f32 N*128]
// ---------------------------------------------------------------------------
extern "C" void kernel_launch(void* const* d_in, const int* in_sizes, int n_in,
                              void* d_out, int out_size) {
    const float* x    = (const float*)d_in[0];
    const int*   esrc = (const int*)d_in[1];
    const int*   edst = (const int*)d_in[2];
    const float* ew   = (const float*)d_in[3];
    const float* W    = (const float*)d_in[4];
    float* out = (float*)d_out;

    const int nE = in_sizes[1];

    __half* support; cudaGetSymbolAddress((void**)&support, g_support);
    int*    cnt;     cudaGetSymbolAddress((void**)&cnt,     g_cnt);

    const int edgeBlocks = (nE + 255) / 256;

    // 1) zero histogram (memset node — graph-capturable)
    cudaMemsetAsync(cnt, 0, N_NODES * sizeof(int));

    // 2) support = x @ W  (mma.sync bf16 hi/lo split, 3 passes; fp16 output)
    cudaFuncSetAttribute(gemm_mma_kernel,
                         cudaFuncAttributeMaxDynamicSharedMemorySize, SM_TOTAL);
    gemm_mma_kernel<<<(N_NODES + 127) / 128, 256, SM_TOTAL>>>(x, W, support, N_NODES);

    // 3) counting sort of edges by dst
    hist_kernel<<<edgeBlocks, 256>>>(edst, nE);
    scan_kernel<<<1, 1024>>>();
    fill_kernel<<<edgeBlocks, 256>>>(esrc, edst, ew, nE);

    // 4) segmented accumulate: one warp per node, no atomics
    {
        long long totalThreads = (long long)N_NODES * 32;
        int blocks = (int)((totalThreads + 255) / 256);
        gather_kernel<<<blocks, 256>>>(support, out);
    }
}